// round 6
// baseline (speedup 1.0000x reference)
#include <cuda_runtime.h>
#include <cstdint>

// ============================================================================
// Geodesic patch conv via frequency domain (NDIRS=16 circular correlation):
//   Yhat[v,rc,b]   = DFT_16(y[v,rc,:])           (9 half-spectrum bins)
//   Chat[v,f,b]    = sum_rc Yhat[v,rc,b] * G[rc,b,f]   (G = scaled conj DFT of K)
//   out[v,j,f]     = relu( bias[f] + sum_b Re{ Chat_b e^{+i 2pi jb/16} } )
// All twiddles are multiples of 22.5 deg -> compile-time immediates (FFMA-imm rt=1).
// ============================================================================

#define NVv     50000
#define NVERT   200000
#define VPB     16
#define THREADS 256

// cos(k * 22.5 deg), k = 0..15.  sin(k*22.5) = C16[(k+12)&15]
__device__ constexpr float C16[16] = {
     1.0f,                  0.9238795325112867f,  0.7071067811865476f,  0.3826834323650898f,
     0.0f,                 -0.3826834323650898f, -0.7071067811865476f, -0.9238795325112867f,
    -1.0f,                 -0.9238795325112867f, -0.7071067811865476f, -0.3826834323650898f,
     0.0f,                  0.3826834323650898f,  0.7071067811865476f,  0.9238795325112867f };

// G[rc][b][f] as float4 {Gr, Gi, -Gi, Gr}, pre-scaled by s_b (1/16 or 2/16)
__device__ __align__(16) float4 g_G[9 * 9 * 16];

// Packed fp32x2 FMA (Blackwell, proven to compile on this target in R2)
#define FMA_F32X2(acc, a, b) \
    asm("fma.rn.f32x2 %0, %1, %2, %0;" : "+l"(acc) : "l"(a), "l"(b))
#define UNPACK_F32X2(lo, hi, in) \
    asm("mov.b64 {%0, %1}, %2;" : "=r"(lo), "=r"(hi) : "l"(in))

// smem byte offsets
#define OFF_GS  0                       // 1296 float4 = 20736 B
#define OFF_YS  20736                   // 16 * 153 floats = 9792 B
#define OFF_YH  30528                   // 16 * 81 float4 = 20736 B
#define OFF_BS  51264                   // 16 floats
#define SMEMSZ  51328

// ---------------- pre-kernel: G = s_b * conj(DFT_16(k)) ----------------
__global__ void build_G_kernel(const float* __restrict__ kern) {
    int idx = blockIdx.x * 256 + threadIdx.x;
    if (idx >= 9 * 9 * 16) return;
    int f  = idx & 15;
    int b  = (idx >> 4) % 9;
    int rc = idx / 144;
    int r = rc / 3, c = rc - 3 * r;
    float gr = 0.0f, gi = 0.0f;
    for (int w = 0; w < 16; w++) {
        float k = kern[((r * 16 + w) * 3 + c) * 16 + f];
        gr += k * C16[(w * b) & 15];           // sum k cos
        gi += k * C16[((w * b) + 12) & 15];    // sum k sin
    }
    float s = (b == 0 || b == 8) ? (1.0f / 16.0f) : (2.0f / 16.0f);
    g_G[idx] = make_float4(gr * s, gi * s, -gi * s, gr * s);
}

// ---------------- main kernel ----------------
__global__ void __launch_bounds__(THREADS)
geoconv_fft_kernel(const float* __restrict__ basepoints,   // (B*NV, 3)
                   const float* __restrict__ frames,       // (B*NV, 3, 3)
                   const int*   __restrict__ expmap,       // (B*NV, 3, 16, 2)
                   const float* __restrict__ bias,         // (16,)
                   float* __restrict__ out)                // (B*NV, 16, 16)
{
    extern __shared__ char smem[];
    float4* Gs = reinterpret_cast<float4*>(smem + OFF_GS);
    float*  ys = reinterpret_cast<float*>(smem + OFF_YS);   // [vl][rc*17 + p]
    float4* Yh = reinterpret_cast<float4*>(smem + OFF_YH);  // [vl][rc*9 + b]
    float*  bs = reinterpret_cast<float*>(smem + OFF_BS);

    const int tid = threadIdx.x;
    const int vl  = tid >> 4;
    const int ln  = tid & 15;
    const int g   = blockIdx.x * VPB + vl;

    // stage G and bias
    #pragma unroll
    for (int it = 0; it < 6; it++) {
        int i = tid + it * THREADS;
        if (i < 1296) Gs[i] = g_G[i];
    }
    if (tid < 16) bs[tid] = bias[tid];

    // --- P1: gather + center + rotate (R2-proven), thread = (vl, d=ln) ---
    {
        const float bp0 = basepoints[g * 3 + 0];
        const float bp1 = basepoints[g * 3 + 1];
        const float bp2 = basepoints[g * 3 + 2];
        float F[9];
        #pragma unroll
        for (int i = 0; i < 9; i++) F[i] = frames[g * 9 + i];

        const int2* em = reinterpret_cast<const int2*>(expmap);
        #pragma unroll
        for (int r = 0; r < 3; r++) {
            int2 e = em[(g * 3 + r) * 16 + ln];            // {batch, vertex}
            const float* nb = basepoints + (e.x * NVv + e.y) * 3;
            float y0 = nb[0] - bp0;
            float y1 = nb[1] - bp1;
            float y2 = nb[2] - bp2;
            #pragma unroll
            for (int k = 0; k < 3; k++) {
                float yr = fmaf(F[k * 3 + 2], y2,
                           fmaf(F[k * 3 + 1], y1, F[k * 3 + 0] * y0));
                ys[vl * 153 + (r * 3 + k) * 17 + ln] = yr;
            }
        }
    }
    __syncthreads();

    // --- P1b: 9-bin real DFT per (vl, rc), immediate twiddles ---
    if (ln < 9) {
        const int rc = ln;
        float yv[16];
        const float* yr = ys + vl * 153 + rc * 17;
        #pragma unroll
        for (int p = 0; p < 16; p++) yv[p] = yr[p];
        float4* dst = Yh + vl * 81 + rc * 9;
        #pragma unroll
        for (int b = 0; b < 9; b++) {
            float re = 0.0f, im = 0.0f;
            #pragma unroll
            for (int p = 0; p < 16; p++) {
                re = fmaf(yv[p],  C16[(p * b) & 15], re);         // + y cos
                im = fmaf(yv[p], -C16[((p * b) + 12) & 15], im);  // - y sin
            }
            dst[b] = make_float4(re, re, im, im);
        }
    }
    __syncthreads();

    // --- P2a: Chat_b = sum_rc Yhat * G   (thread = (vl, f=ln)) ---
    unsigned long long acc[9];
    #pragma unroll
    for (int b = 0; b < 9; b++) acc[b] = 0ull;   // (+0.0f, +0.0f)

    const ulonglong2* Yv = reinterpret_cast<const ulonglong2*>(Yh + vl * 81);
    const ulonglong2* Gv = reinterpret_cast<const ulonglong2*>(Gs);
    #pragma unroll
    for (int rc = 0; rc < 9; rc++) {
        #pragma unroll
        for (int b = 0; b < 9; b++) {
            ulonglong2 Yq = Yv[rc * 9 + b];             // (Yr,Yr),(Yi,Yi)
            ulonglong2 Gq = Gv[(rc * 9 + b) * 16 + ln]; // (Gr,Gi),(-Gi,Gr)
            FMA_F32X2(acc[b], Yq.x, Gq.x);
            FMA_F32X2(acc[b], Yq.y, Gq.y);
        }
    }

    // --- P2b: half-spectrum inverse DFT over j, immediate twiddles ---
    float Cr[9], Ci[9];
    #pragma unroll
    for (int b = 0; b < 9; b++) {
        unsigned int lo, hi;
        UNPACK_F32X2(lo, hi, acc[b]);
        Cr[b] = __uint_as_float(lo);
        Ci[b] = __uint_as_float(hi);
    }

    const float bf = bs[ln];
    float o[16];
    #pragma unroll
    for (int j = 0; j < 16; j++) o[j] = bf;
    #pragma unroll
    for (int b = 0; b < 9; b++) {
        #pragma unroll
        for (int j = 0; j < 16; j++) {
            o[j] = fmaf(Cr[b],  C16[(j * b) & 15], o[j]);         // + Cr cos
            o[j] = fmaf(Ci[b], -C16[((j * b) + 12) & 15], o[j]);  // - Ci sin
        }
    }

    // --- relu + store: out[g][j][f] ---
    float* op = out + (g * 16) * 16 + ln;
    #pragma unroll
    for (int j = 0; j < 16; j++) op[j * 16] = fmaxf(o[j], 0.0f);
}

// ---------------- launch ----------------
extern "C" void kernel_launch(void* const* d_in, const int* in_sizes, int n_in,
                              void* d_out, int out_size)
{
    const float* basepoints = (const float*)d_in[0];   // (B, NV, 3)
    const float* frames     = (const float*)d_in[1];   // (B, NV, 3, 3)
    const int*   expmap     = (const int*)  d_in[2];   // (B, NV, 3, 16, 2)
    const float* kern       = (const float*)d_in[3];   // (3, 16, 3, 16)
    const float* bias       = (const float*)d_in[4];   // (16,)
    float*       out        = (float*)d_out;           // (B, NV, 16, 16)

    cudaFuncSetAttribute(geoconv_fft_kernel,
                         cudaFuncAttributeMaxDynamicSharedMemorySize, SMEMSZ);

    int total_verts = in_sizes[0] / 3;                 // 200000
    int blocks = total_verts / VPB;                    // 12500

    build_G_kernel<<<6, 256>>>(kern);
    geoconv_fft_kernel<<<blocks, THREADS, SMEMSZ>>>(basepoints, frames, expmap, bias, out);
}

// round 7
// speedup vs baseline: 1.2545x; 1.2545x over previous
#include <cuda_runtime.h>
#include <cstdint>

// ============================================================================
// Geodesic patch conv via frequency domain (NDIRS=16 circular correlation):
//   Yhat[v,rc,b] = DFT_16(y[v,rc,:])   (9 half-spectrum bins, packed re,re,im,im)
//   out[v,j,f]   = relu( bias[f] + sum_b Re{ (sum_rc Yhat*G) e^{+i 2pi jb/16} } )
// Twiddles are multiples of 22.5deg -> compile-time immediates.
// P2 processes 2 vertices/thread to amortize G loads; P2a/P2b fused over b.
// ============================================================================

#define NVv     50000
#define NVERT   200000
#define VPB     32
#define THREADS 288            // 9 warps; 32*9=288 exact for P1b

// cos(k * 22.5 deg), k = 0..15.  sin(k*22.5) = C16[(k+12)&15]
__device__ constexpr float C16[16] = {
     1.0f,                  0.9238795325112867f,  0.7071067811865476f,  0.3826834323650898f,
     0.0f,                 -0.3826834323650898f, -0.7071067811865476f, -0.9238795325112867f,
    -1.0f,                 -0.9238795325112867f, -0.7071067811865476f, -0.3826834323650898f,
     0.0f,                  0.3826834323650898f,  0.7071067811865476f,  0.9238795325112867f };

// G[rc][b][f] as float4 {Gr, Gi, -Gi, Gr}, pre-scaled by s_b (1/16 or 2/16)
__device__ __align__(16) float4 g_G[9 * 9 * 16];

#define FMA_F32X2(acc, a, b) \
    asm("fma.rn.f32x2 %0, %1, %2, %0;" : "+l"(acc) : "l"(a), "l"(b))
#define UNPACK_F32X2(lo, hi, in) \
    asm("mov.b64 {%0, %1}, %2;" : "=r"(lo), "=r"(hi) : "l"(in))

// smem byte offsets
#define OFF_GS  0                        // 1296 float4 = 20736 B
#define OFF_YS  20736                    // 32 * 153 floats = 19584 B
#define OFF_YH  40320                    // 32 * 81 float4 = 41472 B
#define OFF_BS  81792                    // 16 floats
#define SMEMSZ  81856

// ---------------- pre-kernel: G = s_b * conj(DFT_16(k)) ----------------
__global__ void build_G_kernel(const float* __restrict__ kern) {
    int idx = blockIdx.x * 256 + threadIdx.x;
    if (idx >= 9 * 9 * 16) return;
    int f  = idx & 15;
    int b  = (idx >> 4) % 9;
    int rc = idx / 144;
    int r = rc / 3, c = rc - 3 * r;
    float gr = 0.0f, gi = 0.0f;
    for (int w = 0; w < 16; w++) {
        float k = kern[((r * 16 + w) * 3 + c) * 16 + f];
        gr += k * C16[(w * b) & 15];           // sum k cos
        gi += k * C16[((w * b) + 12) & 15];    // sum k sin
    }
    float s = (b == 0 || b == 8) ? (1.0f / 16.0f) : (2.0f / 16.0f);
    g_G[idx] = make_float4(gr * s, gi * s, -gi * s, gr * s);
}

// ---------------- main kernel ----------------
__global__ void __launch_bounds__(THREADS)
geoconv_fft_kernel(const float* __restrict__ basepoints,   // (B*NV, 3)
                   const float* __restrict__ frames,       // (B*NV, 3, 3)
                   const int*   __restrict__ expmap,       // (B*NV, 3, 16, 2)
                   const float* __restrict__ bias,         // (16,)
                   float* __restrict__ out)                // (B*NV, 16, 16)
{
    extern __shared__ char smem[];
    float4* Gs = reinterpret_cast<float4*>(smem + OFF_GS);
    float*  ys = reinterpret_cast<float*>(smem + OFF_YS);   // [v][rc*17 + p]
    float4* Yh = reinterpret_cast<float4*>(smem + OFF_YH);  // [v][rc*9 + b]
    float*  bs = reinterpret_cast<float*>(smem + OFF_BS);

    const int tid = threadIdx.x;
    const int gbase = blockIdx.x * VPB;

    // stage G and bias
    #pragma unroll
    for (int it = 0; it < 5; it++) {
        int i = tid + it * THREADS;
        if (i < 1296) Gs[i] = g_G[i];
    }
    if (tid < 16) bs[tid] = bias[tid];

    // --- P1: gather + center + rotate; slot = (vl, d), 512 slots / 288 thr ---
    for (int s = tid; s < VPB * 16; s += THREADS) {
        const int vl = s >> 4;
        const int d  = s & 15;
        const int g  = gbase + vl;
        const float bp0 = basepoints[g * 3 + 0];
        const float bp1 = basepoints[g * 3 + 1];
        const float bp2 = basepoints[g * 3 + 2];
        float F[9];
        #pragma unroll
        for (int i = 0; i < 9; i++) F[i] = frames[g * 9 + i];

        const int2* em = reinterpret_cast<const int2*>(expmap);
        #pragma unroll
        for (int r = 0; r < 3; r++) {
            int2 e = em[(g * 3 + r) * 16 + d];             // {batch, vertex}
            const float* nb = basepoints + (e.x * NVv + e.y) * 3;
            float y0 = nb[0] - bp0;
            float y1 = nb[1] - bp1;
            float y2 = nb[2] - bp2;
            #pragma unroll
            for (int k = 0; k < 3; k++) {
                float yr = fmaf(F[k * 3 + 2], y2,
                           fmaf(F[k * 3 + 1], y1, F[k * 3 + 0] * y0));
                ys[vl * 153 + (r * 3 + k) * 17 + d] = yr;
            }
        }
    }
    __syncthreads();

    // --- P1b: 9-bin real DFT; thread = (v, rc), 32*9 = 288 exact ---
    {
        const int v  = tid / 9;
        const int rc = tid - v * 9;
        float yv[16];
        const float* yr = ys + v * 153 + rc * 17;
        #pragma unroll
        for (int p = 0; p < 16; p++) yv[p] = yr[p];
        float4* dst = Yh + v * 81 + rc * 9;
        #pragma unroll
        for (int b = 0; b < 9; b++) {
            float re = 0.0f, im = 0.0f;
            #pragma unroll
            for (int p = 0; p < 16; p++) {
                re = fmaf(yv[p],  C16[(p * b) & 15], re);         // + y cos
                im = fmaf(yv[p], -C16[((p * b) + 12) & 15], im);  // - y sin
            }
            dst[b] = make_float4(re, re, im, im);
        }
    }
    __syncthreads();

    // --- P2 (fused): thread = (pair, f) handles vertices v0=2*pair, v1=v0+1 ---
    if (tid < 256) {
        const int f    = tid & 15;
        const int pair = tid >> 4;            // 0..15
        const int v0   = 2 * pair;
        const int v1   = v0 + 1;

        const float bf = bs[f];
        float o0[16], o1[16];
        #pragma unroll
        for (int j = 0; j < 16; j++) { o0[j] = bf; o1[j] = bf; }

        const ulonglong2* Gv = reinterpret_cast<const ulonglong2*>(Gs);
        const ulonglong2* Y0 = reinterpret_cast<const ulonglong2*>(Yh + v0 * 81);
        const ulonglong2* Y1 = reinterpret_cast<const ulonglong2*>(Yh + v1 * 81);

        #pragma unroll
        for (int b = 0; b < 9; b++) {
            unsigned long long a0 = 0ull, a1 = 0ull;     // (Cr, Ci) packed
            #pragma unroll
            for (int rc = 0; rc < 9; rc++) {
                ulonglong2 Gq  = Gv[(rc * 9 + b) * 16 + f];  // (Gr,Gi),(-Gi,Gr)
                ulonglong2 Yq0 = Y0[rc * 9 + b];             // (Yr,Yr),(Yi,Yi)
                ulonglong2 Yq1 = Y1[rc * 9 + b];
                FMA_F32X2(a0, Yq0.x, Gq.x);
                FMA_F32X2(a0, Yq0.y, Gq.y);
                FMA_F32X2(a1, Yq1.x, Gq.x);
                FMA_F32X2(a1, Yq1.y, Gq.y);
            }
            unsigned int l0, h0, l1, h1;
            UNPACK_F32X2(l0, h0, a0);
            UNPACK_F32X2(l1, h1, a1);
            float Cr0 = __uint_as_float(l0), Ci0 = __uint_as_float(h0);
            float Cr1 = __uint_as_float(l1), Ci1 = __uint_as_float(h1);
            #pragma unroll
            for (int j = 0; j < 16; j++) {
                o0[j] = fmaf(Cr0,  C16[(j * b) & 15], o0[j]);
                o0[j] = fmaf(Ci0, -C16[((j * b) + 12) & 15], o0[j]);
                o1[j] = fmaf(Cr1,  C16[(j * b) & 15], o1[j]);
                o1[j] = fmaf(Ci1, -C16[((j * b) + 12) & 15], o1[j]);
            }
        }

        // relu + store: out[g][j][f]
        float* op0 = out + ((gbase + v0) * 16) * 16 + f;
        float* op1 = out + ((gbase + v1) * 16) * 16 + f;
        #pragma unroll
        for (int j = 0; j < 16; j++) {
            op0[j * 16] = fmaxf(o0[j], 0.0f);
            op1[j * 16] = fmaxf(o1[j], 0.0f);
        }
    }
}

// ---------------- launch ----------------
extern "C" void kernel_launch(void* const* d_in, const int* in_sizes, int n_in,
                              void* d_out, int out_size)
{
    const float* basepoints = (const float*)d_in[0];   // (B, NV, 3)
    const float* frames     = (const float*)d_in[1];   // (B, NV, 3, 3)
    const int*   expmap     = (const int*)  d_in[2];   // (B, NV, 3, 16, 2)
    const float* kern       = (const float*)d_in[3];   // (3, 16, 3, 16)
    const float* bias       = (const float*)d_in[4];   // (16,)
    float*       out        = (float*)d_out;           // (B, NV, 16, 16)

    cudaFuncSetAttribute(geoconv_fft_kernel,
                         cudaFuncAttributeMaxDynamicSharedMemorySize, SMEMSZ);

    int total_verts = in_sizes[0] / 3;                 // 200000
    int blocks = total_verts / VPB;                    // 6250

    build_G_kernel<<<6, 256>>>(kern);
    geoconv_fft_kernel<<<blocks, THREADS, SMEMSZ>>>(basepoints, frames, expmap, bias, out);
}

// round 8
// speedup vs baseline: 1.5693x; 1.2509x over previous
#include <cuda_runtime.h>
#include <cstdint>

// ============================================================================
// Geodesic patch conv via frequency domain (NDIRS=16 circular correlation):
//   Yhat[v,rc,b] = DFT_16(y[v,rc,:])   (9 half-spectrum bins, float2 re,im)
//   out[v,j,f]   = relu( bias[f] + sum_b Re{ (sum_rc Yhat*G) e^{+i 2pi jb/16} } )
// Twiddles are multiples of 22.5deg -> compile-time immediates.
// basepoints pre-packed to float4 so each gather is one LDG.128.
// ============================================================================

#define NVv     50000
#define NVERT   200000
#define VPB     32
#define THREADS 288            // 9 warps; 32*9=288 exact for P1b

// cos(k * 22.5 deg), k = 0..15.  sin(k*22.5) = C16[(k+12)&15]
__device__ constexpr float C16[16] = {
     1.0f,                  0.9238795325112867f,  0.7071067811865476f,  0.3826834323650898f,
     0.0f,                 -0.3826834323650898f, -0.7071067811865476f, -0.9238795325112867f,
    -1.0f,                 -0.9238795325112867f, -0.7071067811865476f, -0.3826834323650898f,
     0.0f,                  0.3826834323650898f,  0.7071067811865476f,  0.9238795325112867f };

// G[rc][b][f] as float4 {Gr, Gi, -Gi, Gr}, pre-scaled by s_b (1/16 or 2/16)
__device__ __align__(16) float4 g_G[9 * 9 * 16];
// basepoints padded to float4 for single-LDG.128 gathers
__device__ __align__(16) float4 g_bp4[NVERT];

#define FMA_F32X2(acc, a, b) \
    asm("fma.rn.f32x2 %0, %1, %2, %0;" : "+l"(acc) : "l"(a), "l"(b))
#define PACK_F32X2(out, lo, hi) \
    asm("mov.b64 %0, {%1, %2};" : "=l"(out) : "r"(lo), "r"(hi))
#define UNPACK_F32X2(lo, hi, in) \
    asm("mov.b64 {%0, %1}, %2;" : "=r"(lo), "=r"(hi) : "l"(in))

// smem byte offsets
#define OFF_GS  0                        // 1296 float4 = 20736 B
#define OFF_YS  20736                    // 32 * 153 floats = 19584 B
#define OFF_YH  40320                    // 32 * 81 float2 = 20736 B
#define OFF_BS  61056                    // 16 floats
#define SMEMSZ  61120

// ---------------- pre-kernel: pack basepoints to float4 ----------------
__global__ void build_bp4_kernel(const float* __restrict__ basepoints) {
    int i = blockIdx.x * 256 + threadIdx.x;
    if (i >= NVERT) return;
    g_bp4[i] = make_float4(basepoints[i * 3 + 0], basepoints[i * 3 + 1],
                           basepoints[i * 3 + 2], 0.0f);
}

// ---------------- pre-kernel: G = s_b * conj(DFT_16(k)) ----------------
__global__ void build_G_kernel(const float* __restrict__ kern) {
    int idx = blockIdx.x * 256 + threadIdx.x;
    if (idx >= 9 * 9 * 16) return;
    int f  = idx & 15;
    int b  = (idx >> 4) % 9;
    int rc = idx / 144;
    int r = rc / 3, c = rc - 3 * r;
    float gr = 0.0f, gi = 0.0f;
    for (int w = 0; w < 16; w++) {
        float k = kern[((r * 16 + w) * 3 + c) * 16 + f];
        gr += k * C16[(w * b) & 15];           // sum k cos
        gi += k * C16[((w * b) + 12) & 15];    // sum k sin
    }
    float s = (b == 0 || b == 8) ? (1.0f / 16.0f) : (2.0f / 16.0f);
    g_G[idx] = make_float4(gr * s, gi * s, -gi * s, gr * s);
}

// ---------------- main kernel ----------------
__global__ void __launch_bounds__(THREADS, 3)
geoconv_fft_kernel(const float* __restrict__ frames,       // (B*NV, 3, 3)
                   const int*   __restrict__ expmap,       // (B*NV, 3, 16, 2)
                   const float* __restrict__ bias,         // (16,)
                   float* __restrict__ out)                // (B*NV, 16, 16)
{
    extern __shared__ char smem[];
    float4* Gs = reinterpret_cast<float4*>(smem + OFF_GS);
    float*  ys = reinterpret_cast<float*>(smem + OFF_YS);   // [v][rc*17 + p]
    float2* Yh = reinterpret_cast<float2*>(smem + OFF_YH);  // [v][rc*9 + b]
    float*  bs = reinterpret_cast<float*>(smem + OFF_BS);

    const int tid = threadIdx.x;
    const int gbase = blockIdx.x * VPB;

    // stage G and bias
    #pragma unroll
    for (int it = 0; it < 5; it++) {
        int i = tid + it * THREADS;
        if (i < 1296) Gs[i] = g_G[i];
    }
    if (tid < 16) bs[tid] = bias[tid];

    // --- P1: gather + center + rotate; slot = (vl, d), 512 slots / 288 thr ---
    for (int s = tid; s < VPB * 16; s += THREADS) {
        const int vl = s >> 4;
        const int d  = s & 15;
        const int g  = gbase + vl;
        const float4 bp = g_bp4[g];            // broadcast within 16-lane group
        float F[9];
        #pragma unroll
        for (int i = 0; i < 9; i++) F[i] = frames[g * 9 + i];

        const int2* em = reinterpret_cast<const int2*>(expmap);
        #pragma unroll
        for (int r = 0; r < 3; r++) {
            int2 e = em[(g * 3 + r) * 16 + d];             // {batch, vertex}
            float4 nb = g_bp4[e.x * NVv + e.y];            // single LDG.128
            float y0 = nb.x - bp.x;
            float y1 = nb.y - bp.y;
            float y2 = nb.z - bp.z;
            #pragma unroll
            for (int k = 0; k < 3; k++) {
                float yr = fmaf(F[k * 3 + 2], y2,
                           fmaf(F[k * 3 + 1], y1, F[k * 3 + 0] * y0));
                ys[vl * 153 + (r * 3 + k) * 17 + d] = yr;
            }
        }
    }
    __syncthreads();

    // --- P1b: 9-bin real DFT; thread = (v, rc), 32*9 = 288 exact ---
    {
        const int v  = tid / 9;
        const int rc = tid - v * 9;
        float yv[16];
        const float* yr = ys + v * 153 + rc * 17;
        #pragma unroll
        for (int p = 0; p < 16; p++) yv[p] = yr[p];
        float2* dst = Yh + v * 81 + rc * 9;
        #pragma unroll
        for (int b = 0; b < 9; b++) {
            float re = 0.0f, im = 0.0f;
            #pragma unroll
            for (int p = 0; p < 16; p++) {
                re = fmaf(yv[p],  C16[(p * b) & 15], re);         // + y cos
                im = fmaf(yv[p], -C16[((p * b) + 12) & 15], im);  // - y sin
            }
            dst[b] = make_float2(re, im);
        }
    }
    __syncthreads();

    // --- P2 (fused): thread = (pair, f) handles vertices v0=2*pair, v1=v0+1 ---
    if (tid < 256) {
        const int f    = tid & 15;
        const int pair = tid >> 4;            // 0..15
        const int v0   = 2 * pair;
        const int v1   = v0 + 1;

        const float bf = bs[f];
        float o0[16], o1[16];
        #pragma unroll
        for (int j = 0; j < 16; j++) { o0[j] = bf; o1[j] = bf; }

        const ulonglong2* Gv = reinterpret_cast<const ulonglong2*>(Gs);
        const float2* Y0 = Yh + v0 * 81;
        const float2* Y1 = Yh + v1 * 81;

        #pragma unroll
        for (int b = 0; b < 9; b++) {
            unsigned long long a0 = 0ull, a1 = 0ull;     // (Cr, Ci) packed
            #pragma unroll
            for (int rc = 0; rc < 9; rc++) {
                ulonglong2 Gq = Gv[(rc * 9 + b) * 16 + f];  // (Gr,Gi),(-Gi,Gr)
                float2 q0 = Y0[rc * 9 + b];                 // (Yr, Yi) broadcast
                float2 q1 = Y1[rc * 9 + b];
                unsigned long long y0rr, y0ii, y1rr, y1ii;
                PACK_F32X2(y0rr, __float_as_uint(q0.x), __float_as_uint(q0.x));
                PACK_F32X2(y0ii, __float_as_uint(q0.y), __float_as_uint(q0.y));
                PACK_F32X2(y1rr, __float_as_uint(q1.x), __float_as_uint(q1.x));
                PACK_F32X2(y1ii, __float_as_uint(q1.y), __float_as_uint(q1.y));
                FMA_F32X2(a0, y0rr, Gq.x);
                FMA_F32X2(a0, y0ii, Gq.y);
                FMA_F32X2(a1, y1rr, Gq.x);
                FMA_F32X2(a1, y1ii, Gq.y);
            }
            unsigned int l0, h0, l1, h1;
            UNPACK_F32X2(l0, h0, a0);
            UNPACK_F32X2(l1, h1, a1);
            float Cr0 = __uint_as_float(l0), Ci0 = __uint_as_float(h0);
            float Cr1 = __uint_as_float(l1), Ci1 = __uint_as_float(h1);
            #pragma unroll
            for (int j = 0; j < 16; j++) {
                o0[j] = fmaf(Cr0,  C16[(j * b) & 15], o0[j]);
                o0[j] = fmaf(Ci0, -C16[((j * b) + 12) & 15], o0[j]);
                o1[j] = fmaf(Cr1,  C16[(j * b) & 15], o1[j]);
                o1[j] = fmaf(Ci1, -C16[((j * b) + 12) & 15], o1[j]);
            }
        }

        // relu + store: out[g][j][f]
        float* op0 = out + ((gbase + v0) * 16) * 16 + f;
        float* op1 = out + ((gbase + v1) * 16) * 16 + f;
        #pragma unroll
        for (int j = 0; j < 16; j++) {
            op0[j * 16] = fmaxf(o0[j], 0.0f);
            op1[j * 16] = fmaxf(o1[j], 0.0f);
        }
    }
}

// ---------------- launch ----------------
extern "C" void kernel_launch(void* const* d_in, const int* in_sizes, int n_in,
                              void* d_out, int out_size)
{
    const float* basepoints = (const float*)d_in[0];   // (B, NV, 3)
    const float* frames     = (const float*)d_in[1];   // (B, NV, 3, 3)
    const int*   expmap     = (const int*)  d_in[2];   // (B, NV, 3, 16, 2)
    const float* kern       = (const float*)d_in[3];   // (3, 16, 3, 16)
    const float* bias       = (const float*)d_in[4];   // (16,)
    float*       out        = (float*)d_out;           // (B, NV, 16, 16)

    cudaFuncSetAttribute(geoconv_fft_kernel,
                         cudaFuncAttributeMaxDynamicSharedMemorySize, SMEMSZ);

    int total_verts = in_sizes[0] / 3;                 // 200000
    int blocks = total_verts / VPB;                    // 6250

    build_bp4_kernel<<<(NVERT + 255) / 256, 256>>>(basepoints);
    build_G_kernel<<<6, 256>>>(kern);
    geoconv_fft_kernel<<<blocks, THREADS, SMEMSZ>>>(frames, expmap, bias, out);
}

// round 9
// speedup vs baseline: 1.7796x; 1.1340x over previous
#include <cuda_runtime.h>
#include <cstdint>

// ============================================================================
// Geodesic patch conv via frequency domain (NDIRS=16 circular correlation):
//   Yhat[v,rc,b] = DFT_16(y[v,rc,:])   (9 half-spectrum bins, (re,im) float2)
//   out[v,j,f]   = relu( bias[f] + sum_b Re{ (sum_rc Yhat*G) e^{+i 2pi jb/16} } )
// P2: thread = (vertex, f-pair); G packed (Gr0,Gr1,Gi0,Gi1) -> 1-wavefront LDS.
// ============================================================================

#define NVv     50000
#define NVERT   200000
#define VPB     32
#define THREADS 288            // 9 warps; 32*9=288 exact for P1b

// cos(k * 22.5 deg), k = 0..15.  sin(k*22.5) = C16[(k+12)&15]
__device__ constexpr float C16[16] = {
     1.0f,                  0.9238795325112867f,  0.7071067811865476f,  0.3826834323650898f,
     0.0f,                 -0.3826834323650898f, -0.7071067811865476f, -0.9238795325112867f,
    -1.0f,                 -0.9238795325112867f, -0.7071067811865476f, -0.3826834323650898f,
     0.0f,                  0.3826834323650898f,  0.7071067811865476f,  0.9238795325112867f };

// G4[b][rc][fp] = {Gr(2fp), Gr(2fp+1), Gi(2fp), Gi(2fp+1)}, pre-scaled by s_b
__device__ __align__(16) float4 g_G4[9 * 9 * 8];
// basepoints padded to float4; frames padded to 3x float4 (rows)
__device__ __align__(16) float4 g_bp4[NVERT];
__device__ __align__(16) float4 g_fr4[NVERT * 3];

#define FMA_F32X2(acc, a, b) \
    asm("fma.rn.f32x2 %0, %1, %2, %0;" : "+l"(acc) : "l"(a), "l"(b))
#define PACK_F32X2(out, lo, hi) \
    asm("mov.b64 %0, {%1, %2};" : "=l"(out) : "r"(lo), "r"(hi))
#define UNPACK_F32X2(lo, hi, in) \
    asm("mov.b64 {%0, %1}, %2;" : "=r"(lo), "=r"(hi) : "l"(in))

// smem byte offsets
#define OFF_GS  0                        // 648 float4 = 10368 B
#define OFF_YS  10368                    // 32 * 153 floats = 19584 B
#define OFF_YH  29952                    // 32 * 90 float2 = 23040 B
#define OFF_BS  52992                    // 16 floats
#define SMEMSZ  53056

// ---------------- pre-kernel: pack basepoints + frames ----------------
__global__ void build_aux_kernel(const float* __restrict__ basepoints,
                                 const float* __restrict__ frames) {
    int i = blockIdx.x * 256 + threadIdx.x;
    if (i >= NVERT) return;
    g_bp4[i] = make_float4(basepoints[i * 3 + 0], basepoints[i * 3 + 1],
                           basepoints[i * 3 + 2], 0.0f);
    #pragma unroll
    for (int k = 0; k < 3; k++)
        g_fr4[i * 3 + k] = make_float4(frames[i * 9 + k * 3 + 0],
                                       frames[i * 9 + k * 3 + 1],
                                       frames[i * 9 + k * 3 + 2], 0.0f);
}

// ---------------- pre-kernel: G4 = s_b * conj(DFT_16(k)), f-pair packed ----
__global__ void build_G_kernel(const float* __restrict__ kern) {
    int idx = blockIdx.x * 256 + threadIdx.x;     // (b*9 + rc)*8 + fp
    if (idx >= 9 * 9 * 8) return;
    int fp = idx & 7;
    int rc = (idx >> 3) % 9;
    int b  = idx / 72;
    int r = rc / 3, c = rc - 3 * r;
    float gr[2] = {0.0f, 0.0f}, gi[2] = {0.0f, 0.0f};
    for (int w = 0; w < 16; w++) {
        float cw = C16[(w * b) & 15];
        float sw = C16[((w * b) + 12) & 15];
        #pragma unroll
        for (int u = 0; u < 2; u++) {
            float k = kern[((r * 16 + w) * 3 + c) * 16 + (2 * fp + u)];
            gr[u] += k * cw;
            gi[u] += k * sw;
        }
    }
    float s = (b == 0 || b == 8) ? (1.0f / 16.0f) : (2.0f / 16.0f);
    g_G4[idx] = make_float4(gr[0] * s, gr[1] * s, gi[0] * s, gi[1] * s);
}

// one (rc) complex MAC: a_cr += Yr*Gr - Yi*Gi ; a_ci += Yr*Gi + Yi*Gr (f-pairs)
#define RCSTEP(yr, yi, gv) do { \
    unsigned long long _yrr, _yii, _ynn, _ghr, _ghi; \
    unsigned int _nyi = __float_as_uint(yi) ^ 0x80000000u; \
    PACK_F32X2(_yrr, __float_as_uint(yr), __float_as_uint(yr)); \
    PACK_F32X2(_yii, __float_as_uint(yi), __float_as_uint(yi)); \
    PACK_F32X2(_ynn, _nyi, _nyi); \
    PACK_F32X2(_ghr, __float_as_uint((gv).x), __float_as_uint((gv).y)); \
    PACK_F32X2(_ghi, __float_as_uint((gv).z), __float_as_uint((gv).w)); \
    FMA_F32X2(a_cr, _yrr, _ghr); \
    FMA_F32X2(a_cr, _ynn, _ghi); \
    FMA_F32X2(a_ci, _yrr, _ghi); \
    FMA_F32X2(a_ci, _yii, _ghr); \
} while (0)

// ---------------- main kernel ----------------
__global__ void __launch_bounds__(THREADS, 3)
geoconv_fft_kernel(const int*   __restrict__ expmap,       // (B*NV, 3, 16, 2)
                   const float* __restrict__ bias,         // (16,)
                   float* __restrict__ out)                // (B*NV, 16, 16)
{
    extern __shared__ char smem[];
    float4* Gs = reinterpret_cast<float4*>(smem + OFF_GS);
    float*  ys = reinterpret_cast<float*>(smem + OFF_YS);   // [v][rc*17 + p]
    float2* Yh = reinterpret_cast<float2*>(smem + OFF_YH);  // [v][b*10 + rc]
    float*  bs = reinterpret_cast<float*>(smem + OFF_BS);

    const int tid = threadIdx.x;
    const int gbase = blockIdx.x * VPB;

    // stage G4 and bias
    #pragma unroll
    for (int it = 0; it < 3; it++) {
        int i = tid + it * THREADS;
        if (i < 648) Gs[i] = g_G4[i];
    }
    if (tid < 16) bs[tid] = bias[tid];

    // --- P1: gather + center + rotate; slot = (vl, d), 512 slots / 288 thr ---
    for (int s = tid; s < VPB * 16; s += THREADS) {
        const int vl = s >> 4;
        const int d  = s & 15;
        const int g  = gbase + vl;
        const float4 bp = g_bp4[g];
        const float4 F0 = g_fr4[g * 3 + 0];
        const float4 F1 = g_fr4[g * 3 + 1];
        const float4 F2 = g_fr4[g * 3 + 2];

        const int2* em = reinterpret_cast<const int2*>(expmap);
        #pragma unroll
        for (int r = 0; r < 3; r++) {
            int2 e = em[(g * 3 + r) * 16 + d];             // {batch, vertex}
            float4 nb = g_bp4[e.x * NVv + e.y];            // single LDG.128
            float y0 = nb.x - bp.x;
            float y1 = nb.y - bp.y;
            float y2 = nb.z - bp.z;
            float* yrow = ys + vl * 153 + r * 51 + d;
            yrow[0]  = fmaf(F0.z, y2, fmaf(F0.y, y1, F0.x * y0));
            yrow[17] = fmaf(F1.z, y2, fmaf(F1.y, y1, F1.x * y0));
            yrow[34] = fmaf(F2.z, y2, fmaf(F2.y, y1, F2.x * y0));
        }
    }
    __syncthreads();

    // --- P1b: 9-bin real DFT; thread = (v, rc), 32*9 = 288 exact ---
    {
        const int v  = tid / 9;
        const int rc = tid - v * 9;
        float yv[16];
        const float* yr = ys + v * 153 + rc * 17;
        #pragma unroll
        for (int p = 0; p < 16; p++) yv[p] = yr[p];
        float2* dst = Yh + v * 90 + rc;
        #pragma unroll
        for (int b = 0; b < 9; b++) {
            float re = 0.0f, im = 0.0f;
            #pragma unroll
            for (int p = 0; p < 16; p++) {
                re = fmaf(yv[p],  C16[(p * b) & 15], re);         // + y cos
                im = fmaf(yv[p], -C16[((p * b) + 12) & 15], im);  // - y sin
            }
            dst[b * 10] = make_float2(re, im);
        }
    }
    __syncthreads();

    // --- P2 (fused): thread = (v, fp); 1 vertex, features 2fp, 2fp+1 ---
    if (tid < 256) {
        const int fp = tid & 7;
        const int v  = tid >> 3;

        float o0[16], o1[16];
        const float b0 = bs[2 * fp], b1 = bs[2 * fp + 1];
        #pragma unroll
        for (int j = 0; j < 16; j++) { o0[j] = b0; o1[j] = b1; }

        #pragma unroll
        for (int b = 0; b < 9; b++) {
            // load 9 (Yr,Yi) pairs for this (v,b): 4x LDS.128 + 1x LDS.64
            const float4* Yb4 = reinterpret_cast<const float4*>(Yh + v * 90 + b * 10);
            float4 ya = Yb4[0], yb_ = Yb4[1], yc = Yb4[2], yd = Yb4[3];
            float2 ye = *reinterpret_cast<const float2*>(Yh + v * 90 + b * 10 + 8);

            const float4* Gb = Gs + b * 72 + fp;   // [b][rc][fp], rc stride 8
            unsigned long long a_cr = 0ull, a_ci = 0ull;
            RCSTEP(ya.x,  ya.y,  Gb[0]);
            RCSTEP(ya.z,  ya.w,  Gb[8]);
            RCSTEP(yb_.x, yb_.y, Gb[16]);
            RCSTEP(yb_.z, yb_.w, Gb[24]);
            RCSTEP(yc.x,  yc.y,  Gb[32]);
            RCSTEP(yc.z,  yc.w,  Gb[40]);
            RCSTEP(yd.x,  yd.y,  Gb[48]);
            RCSTEP(yd.z,  yd.w,  Gb[56]);
            RCSTEP(ye.x,  ye.y,  Gb[64]);

            unsigned int lr, hr, li, hi_;
            UNPACK_F32X2(lr, hr, a_cr);
            UNPACK_F32X2(li, hi_, a_ci);
            float Cr0 = __uint_as_float(lr), Cr1 = __uint_as_float(hr);
            float Ci0 = __uint_as_float(li), Ci1 = __uint_as_float(hi_);

            #pragma unroll
            for (int j = 0; j < 16; j++) {
                const float cj = C16[(j * b) & 15];
                const float sj = C16[((j * b) + 12) & 15];
                o0[j] = fmaf(Cr0, cj, o0[j]);
                o0[j] = fmaf(Ci0, -sj, o0[j]);
                o1[j] = fmaf(Cr1, cj, o1[j]);
                o1[j] = fmaf(Ci1, -sj, o1[j]);
            }
        }

        // relu + store as float2 (features 2fp, 2fp+1)
        float2* op = reinterpret_cast<float2*>(out + ((gbase + v) * 16) * 16 + 2 * fp);
        #pragma unroll
        for (int j = 0; j < 16; j++)
            op[j * 8] = make_float2(fmaxf(o0[j], 0.0f), fmaxf(o1[j], 0.0f));
    }
}

// ---------------- launch ----------------
extern "C" void kernel_launch(void* const* d_in, const int* in_sizes, int n_in,
                              void* d_out, int out_size)
{
    const float* basepoints = (const float*)d_in[0];   // (B, NV, 3)
    const float* frames     = (const float*)d_in[1];   // (B, NV, 3, 3)
    const int*   expmap     = (const int*)  d_in[2];   // (B, NV, 3, 16, 2)
    const float* kern       = (const float*)d_in[3];   // (3, 16, 3, 16)
    const float* bias       = (const float*)d_in[4];   // (16,)
    float*       out        = (float*)d_out;           // (B, NV, 16, 16)

    cudaFuncSetAttribute(geoconv_fft_kernel,
                         cudaFuncAttributeMaxDynamicSharedMemorySize, SMEMSZ);

    int total_verts = in_sizes[0] / 3;                 // 200000
    int blocks = total_verts / VPB;                    // 6250

    build_aux_kernel<<<(NVERT + 255) / 256, 256>>>(basepoints, frames);
    build_G_kernel<<<3, 256>>>(kern);
    geoconv_fft_kernel<<<blocks, THREADS, SMEMSZ>>>(expmap, bias, out);
}

// round 10
// speedup vs baseline: 1.8689x; 1.0502x over previous
#include <cuda_runtime.h>
#include <cstdint>

// ============================================================================
// Geodesic patch conv via frequency domain (NDIRS=16 circular correlation):
//   Yhat[v,rc,b] = DFT_16(y[v,rc,:])   (9 half-spectrum bins, (re,im) float2)
//   out[v,j,f]   = relu( bias[f] + sum_b Re{ (sum_rc Yhat*G) e^{+i 2pi jb/16} } )
// Radix-2 parity splits halve both DFT stages; twiddles are constexpr imms.
// P2: thread = (vertex, f-pair); G packed (Gr0,Gr1,Gi0,Gi1) -> 1-wavefront LDS.
// ============================================================================

#define NVv     50000
#define NVERT   200000
#define VPB     32
#define THREADS 288            // 9 warps; 32*9=288 exact for P1b

// cos(k * 22.5 deg), k = 0..15.  sin(k*22.5) = C16[(k+12)&15]
__device__ constexpr float C16[16] = {
     1.0f,                  0.9238795325112867f,  0.7071067811865476f,  0.3826834323650898f,
     0.0f,                 -0.3826834323650898f, -0.7071067811865476f, -0.9238795325112867f,
    -1.0f,                 -0.9238795325112867f, -0.7071067811865476f, -0.3826834323650898f,
     0.0f,                  0.3826834323650898f,  0.7071067811865476f,  0.9238795325112867f };

// G4[b][rc][fp] = {Gr(2fp), Gr(2fp+1), Gi(2fp), Gi(2fp+1)}, pre-scaled by s_b
__device__ __align__(16) float4 g_G4[9 * 9 * 8];
// basepoints padded to float4; frames padded to 3x float4 (rows)
__device__ __align__(16) float4 g_bp4[NVERT];
__device__ __align__(16) float4 g_fr4[NVERT * 3];

#define FMA_F32X2(acc, a, b) \
    asm("fma.rn.f32x2 %0, %1, %2, %0;" : "+l"(acc) : "l"(a), "l"(b))
#define PACK_F32X2(out, lo, hi) \
    asm("mov.b64 %0, {%1, %2};" : "=l"(out) : "r"(lo), "r"(hi))
#define UNPACK_F32X2(lo, hi, in) \
    asm("mov.b64 {%0, %1}, %2;" : "=r"(lo), "=r"(hi) : "l"(in))

// smem byte offsets
#define OFF_GS  0                        // 648 float4 = 10368 B
#define OFF_YS  10368                    // 32 * 144 floats = 18432 B  ([v][rc][16])
#define OFF_YH  28800                    // 32 * 90 float2 = 23040 B   ([v][b*10+rc])
#define OFF_BS  51840                    // 16 floats
#define SMEMSZ  51904

// ---------------- pre-kernel: pack basepoints + frames ----------------
__global__ void build_aux_kernel(const float* __restrict__ basepoints,
                                 const float* __restrict__ frames) {
    int i = blockIdx.x * 256 + threadIdx.x;
    if (i >= NVERT) return;
    g_bp4[i] = make_float4(basepoints[i * 3 + 0], basepoints[i * 3 + 1],
                           basepoints[i * 3 + 2], 0.0f);
    #pragma unroll
    for (int k = 0; k < 3; k++)
        g_fr4[i * 3 + k] = make_float4(frames[i * 9 + k * 3 + 0],
                                       frames[i * 9 + k * 3 + 1],
                                       frames[i * 9 + k * 3 + 2], 0.0f);
}

// ---------------- pre-kernel: G4 = s_b * conj(DFT_16(k)), f-pair packed ----
__global__ void build_G_kernel(const float* __restrict__ kern) {
    int idx = blockIdx.x * 256 + threadIdx.x;     // (b*9 + rc)*8 + fp
    if (idx >= 9 * 9 * 8) return;
    int fp = idx & 7;
    int rc = (idx >> 3) % 9;
    int b  = idx / 72;
    int r = rc / 3, c = rc - 3 * r;
    float gr[2] = {0.0f, 0.0f}, gi[2] = {0.0f, 0.0f};
    for (int w = 0; w < 16; w++) {
        float cw = C16[(w * b) & 15];
        float sw = C16[((w * b) + 12) & 15];
        #pragma unroll
        for (int u = 0; u < 2; u++) {
            float k = kern[((r * 16 + w) * 3 + c) * 16 + (2 * fp + u)];
            gr[u] += k * cw;
            gi[u] += k * sw;
        }
    }
    float s = (b == 0 || b == 8) ? (1.0f / 16.0f) : (2.0f / 16.0f);
    g_G4[idx] = make_float4(gr[0] * s, gr[1] * s, gi[0] * s, gi[1] * s);
}

// one (rc) complex MAC: a_cr += Yr*Gr - Yi*Gi ; a_ci += Yr*Gi + Yi*Gr (f-pairs)
#define RCSTEP(yr, yi, gv) do { \
    unsigned long long _yrr, _yii, _ynn, _ghr, _ghi; \
    unsigned int _nyi = __float_as_uint(yi) ^ 0x80000000u; \
    PACK_F32X2(_yrr, __float_as_uint(yr), __float_as_uint(yr)); \
    PACK_F32X2(_yii, __float_as_uint(yi), __float_as_uint(yi)); \
    PACK_F32X2(_ynn, _nyi, _nyi); \
    PACK_F32X2(_ghr, __float_as_uint((gv).x), __float_as_uint((gv).y)); \
    PACK_F32X2(_ghi, __float_as_uint((gv).z), __float_as_uint((gv).w)); \
    FMA_F32X2(a_cr, _yrr, _ghr); \
    FMA_F32X2(a_cr, _ynn, _ghi); \
    FMA_F32X2(a_ci, _yrr, _ghi); \
    FMA_F32X2(a_ci, _yii, _ghr); \
} while (0)

// ---------------- main kernel ----------------
__global__ void __launch_bounds__(THREADS, 3)
geoconv_fft_kernel(const int*   __restrict__ expmap,       // (B*NV, 3, 16, 2)
                   const float* __restrict__ bias,         // (16,)
                   float* __restrict__ out)                // (B*NV, 16, 16)
{
    extern __shared__ char smem[];
    float4* Gs = reinterpret_cast<float4*>(smem + OFF_GS);
    float*  ys = reinterpret_cast<float*>(smem + OFF_YS);   // [v][rc][16]
    float2* Yh = reinterpret_cast<float2*>(smem + OFF_YH);  // [v][b*10 + rc]
    float*  bs = reinterpret_cast<float*>(smem + OFF_BS);

    const int tid = threadIdx.x;
    const int gbase = blockIdx.x * VPB;

    // stage G4 and bias
    #pragma unroll
    for (int it = 0; it < 3; it++) {
        int i = tid + it * THREADS;
        if (i < 648) Gs[i] = g_G4[i];
    }
    if (tid < 16) bs[tid] = bias[tid];

    // --- P1: gather + center + rotate; slot = (vl, d), 512 slots / 288 thr ---
    for (int s = tid; s < VPB * 16; s += THREADS) {
        const int vl = s >> 4;
        const int d  = s & 15;
        const int g  = gbase + vl;
        const float4 bp = g_bp4[g];
        const float4 F0 = g_fr4[g * 3 + 0];
        const float4 F1 = g_fr4[g * 3 + 1];
        const float4 F2 = g_fr4[g * 3 + 2];

        const int2* em = reinterpret_cast<const int2*>(expmap);
        #pragma unroll
        for (int r = 0; r < 3; r++) {
            int2 e = em[(g * 3 + r) * 16 + d];             // {batch, vertex}
            float4 nb = g_bp4[e.x * NVv + e.y];            // single LDG.128
            float y0 = nb.x - bp.x;
            float y1 = nb.y - bp.y;
            float y2 = nb.z - bp.z;
            float* yb = ys + vl * 144 + r * 48 + d;        // [v][rc][16]
            yb[0]  = fmaf(F0.z, y2, fmaf(F0.y, y1, F0.x * y0));
            yb[16] = fmaf(F1.z, y2, fmaf(F1.y, y1, F1.x * y0));
            yb[32] = fmaf(F2.z, y2, fmaf(F2.y, y1, F2.x * y0));
        }
    }
    __syncthreads();

    // --- P1b: 9-bin real DFT with radix-2 parity split; thread = (v, rc) ---
    {
        const int v  = tid / 9;
        const int rc = tid - v * 9;
        const float4* yr4 = reinterpret_cast<const float4*>(ys + v * 144 + rc * 16);
        float4 q0 = yr4[0], q1 = yr4[1], q2 = yr4[2], q3 = yr4[3];
        const float yv[16] = {q0.x, q0.y, q0.z, q0.w, q1.x, q1.y, q1.z, q1.w,
                              q2.x, q2.y, q2.z, q2.w, q3.x, q3.y, q3.z, q3.w};
        float u[8], w[8];
        #pragma unroll
        for (int q = 0; q < 8; q++) {
            u[q] = yv[q] + yv[q + 8];
            w[q] = yv[q] - yv[q + 8];
        }
        float2* dst = Yh + v * 90 + rc;
        #pragma unroll
        for (int b = 0; b < 9; b++) {
            float re = 0.0f, im = 0.0f;
            #pragma unroll
            for (int q = 0; q < 8; q++) {
                const float src = (b & 1) ? w[q] : u[q];
                re = fmaf(src,  C16[(q * b) & 15], re);          // + src cos
                im = fmaf(src, -C16[((q * b) + 12) & 15], im);   // - src sin
            }
            dst[b * 10] = make_float2(re, im);
        }
    }
    __syncthreads();

    // --- P2 (fused): thread = (v, fp); 1 vertex, features 2fp, 2fp+1 ---
    if (tid < 256) {
        const int fp = tid & 7;
        const int v  = tid >> 3;

        // parity-split IDFT accumulators: out[j]=oE+oO, out[j+8]=oE-oO, j=0..7
        float oE0[8], oO0[8], oE1[8], oO1[8];
        const float b0 = bs[2 * fp], b1 = bs[2 * fp + 1];
        #pragma unroll
        for (int j = 0; j < 8; j++) {
            oE0[j] = b0; oE1[j] = b1;
            oO0[j] = 0.0f; oO1[j] = 0.0f;
        }

        #pragma unroll
        for (int b = 0; b < 9; b++) {
            // load 9 (Yr,Yi) pairs for this (v,b): 4x LDS.128 + 1x LDS.64
            const float4* Yb4 = reinterpret_cast<const float4*>(Yh + v * 90 + b * 10);
            float4 ya = Yb4[0], yb_ = Yb4[1], yc = Yb4[2], yd = Yb4[3];
            float2 ye = *reinterpret_cast<const float2*>(Yh + v * 90 + b * 10 + 8);

            const float4* Gb = Gs + b * 72 + fp;   // [b][rc][fp], rc stride 8
            unsigned long long a_cr = 0ull, a_ci = 0ull;
            RCSTEP(ya.x,  ya.y,  Gb[0]);
            RCSTEP(ya.z,  ya.w,  Gb[8]);
            RCSTEP(yb_.x, yb_.y, Gb[16]);
            RCSTEP(yb_.z, yb_.w, Gb[24]);
            RCSTEP(yc.x,  yc.y,  Gb[32]);
            RCSTEP(yc.z,  yc.w,  Gb[40]);
            RCSTEP(yd.x,  yd.y,  Gb[48]);
            RCSTEP(yd.z,  yd.w,  Gb[56]);
            RCSTEP(ye.x,  ye.y,  Gb[64]);

            unsigned int lr, hr, li, hi_;
            UNPACK_F32X2(lr, hr, a_cr);
            UNPACK_F32X2(li, hi_, a_ci);
            float Cr0 = __uint_as_float(lr), Cr1 = __uint_as_float(hr);
            float Ci0 = __uint_as_float(li), Ci1 = __uint_as_float(hi_);

            #pragma unroll
            for (int j = 0; j < 8; j++) {
                const float cj = C16[(j * b) & 15];
                const float sj = C16[((j * b) + 12) & 15];
                if ((b & 1) == 0) {
                    oE0[j] = fmaf(Cr0, cj, oE0[j]);
                    oE0[j] = fmaf(Ci0, -sj, oE0[j]);
                    oE1[j] = fmaf(Cr1, cj, oE1[j]);
                    oE1[j] = fmaf(Ci1, -sj, oE1[j]);
                } else {
                    oO0[j] = fmaf(Cr0, cj, oO0[j]);
                    oO0[j] = fmaf(Ci0, -sj, oO0[j]);
                    oO1[j] = fmaf(Cr1, cj, oO1[j]);
                    oO1[j] = fmaf(Ci1, -sj, oO1[j]);
                }
            }
        }

        // combine parity halves, relu, store (features 2fp, 2fp+1)
        float2* op = reinterpret_cast<float2*>(out + ((gbase + v) * 16) * 16 + 2 * fp);
        #pragma unroll
        for (int j = 0; j < 8; j++) {
            op[j * 8]       = make_float2(fmaxf(oE0[j] + oO0[j], 0.0f),
                                          fmaxf(oE1[j] + oO1[j], 0.0f));
            op[(j + 8) * 8] = make_float2(fmaxf(oE0[j] - oO0[j], 0.0f),
                                          fmaxf(oE1[j] - oO1[j], 0.0f));
        }
    }
}

// ---------------- launch ----------------
extern "C" void kernel_launch(void* const* d_in, const int* in_sizes, int n_in,
                              void* d_out, int out_size)
{
    const float* basepoints = (const float*)d_in[0];   // (B, NV, 3)
    const float* frames     = (const float*)d_in[1];   // (B, NV, 3, 3)
    const int*   expmap     = (const int*)  d_in[2];   // (B, NV, 3, 16, 2)
    const float* kern       = (const float*)d_in[3];   // (3, 16, 3, 16)
    const float* bias       = (const float*)d_in[4];   // (16,)
    float*       out        = (float*)d_out;           // (B, NV, 16, 16)

    cudaFuncSetAttribute(geoconv_fft_kernel,
                         cudaFuncAttributeMaxDynamicSharedMemorySize, SMEMSZ);

    int total_verts = in_sizes[0] / 3;                 // 200000
    int blocks = total_verts / VPB;                    // 6250

    build_aux_kernel<<<(NVERT + 255) / 256, 256>>>(basepoints, frames);
    build_G_kernel<<<3, 256>>>(kern);
    geoconv_fft_kernel<<<blocks, THREADS, SMEMSZ>>>(expmap, bias, out);
}